// round 14
// baseline (speedup 1.0000x reference)
#include <cuda_runtime.h>
#include <cuda_bf16.h>
#include <cstdint>

// Problem constants
#define NN 512
#define CC 512
#define HH 14
#define WW 14
#define HW 196
#define ROI 49
#define RROWS 490            // 10*49
#define TOUT 10
#define CHW 100352           // 512*196
#define KV4 25088            // CHW in 16B units
#define SK1 8                // split-K for fold1 (K-chunk 64)
#define SK2 8                // split-K for fold2 (K-chunk 64)
#define MSPLIT 16            // K splits for main pass
#define KC4 1568             // KV4/MSPLIT (16B units)
#define KSTEP 112            // 16B units per stage step
#define NSTEP 14             // KC4/KSTEP
#define NIMG 8               // images per block in main pass
#define BZ 8                 // bias_final chunks

#define T1E (RROWS * CC)     // 250880
#define T2E (CC * CC)        // 262144

// ---------------- device scratch ----------------
__device__ __align__(16) float g_T1p[SK1 * T1E];
__device__ __align__(16) float g_T2p[SK1 * T2E];
__device__ __align__(16) float g_T1r[T1E];
__device__ __align__(16) float g_T2r[T2E];
__device__ __align__(16) float g_G1p[SK2 * T1E];
__device__ __align__(16) float g_Bsp[TOUT * CHW];
__device__ float g_beta2[CC];
__device__ float g_beta3[CC];
__device__ float g_bfp[TOUT * BZ];
__device__ float g_part[MSPLIT * NN * TOUT];

// packed fp32x2 FMA (Blackwell)
__device__ __forceinline__ unsigned long long ffma2(
    unsigned long long a, unsigned long long b, unsigned long long c)
{
    unsigned long long d;
    asm("fma.rn.f32x2 %0, %1, %2, %3;" : "=l"(d) : "l"(a), "l"(b), "l"(c));
    return d;
}

__device__ __forceinline__ float unpack_sum(unsigned long long v) {
    float lo, hi;
    asm("mov.b64 {%0, %1}, %2;" : "=f"(lo), "=f"(hi) : "l"(v));
    return lo + hi;
}

__device__ __forceinline__ uint32_t smem_u32(const void* p) {
    return (uint32_t)__cvta_generic_to_shared(p);
}

// ---------------- GEMM body (templated A sourcing) --------------------------
// MODE 0: plain A,B. MODE 1: A gathered from heads (U matrix).
template<int MODE, int KCH>
__device__ __forceinline__ void gemm_body_t(
    const float* __restrict__ A, const float* __restrict__ B,
    const float* __restrict__ wn, const float* __restrict__ wr,
    float* __restrict__ Cz, int M, int kbase)
{
    __shared__ float As[16][64];
    __shared__ float Bs[16][64];
    int tid = threadIdx.x;
    int m0 = blockIdx.y * 64;
    int n0 = blockIdx.x * 64;

    int ar  = tid >> 2;
    int acq = tid & 3;
    int bkr = tid >> 4;
    int bnc = (tid & 15) * 4;
    int ty  = tid >> 4;
    int tx  = tid & 15;

    float acc[4][4] = {};
    #pragma unroll 1
    for (int kk = 0; kk < KCH; kk += 16) {
        int k0 = kbase + kk;
        float4 a4 = make_float4(0.f, 0.f, 0.f, 0.f);
        int m = m0 + ar;
        if (m < M) {
            if (MODE == 1) {
                int t = m / ROI, p = m % ROI;
                const float* wsrc = (t < 2) ? wn + t * (CC * ROI) + p
                                            : wr + (t - 2) * (CC * ROI) + p;
                int o = k0 + acq * 4;
                a4.x = wsrc[(o + 0) * ROI];
                a4.y = wsrc[(o + 1) * ROI];
                a4.z = wsrc[(o + 2) * ROI];
                a4.w = wsrc[(o + 3) * ROI];
            } else {
                a4 = *reinterpret_cast<const float4*>(&A[(size_t)m * 512 + k0 + acq * 4]);
            }
        }
        As[acq * 4 + 0][ar] = a4.x;
        As[acq * 4 + 1][ar] = a4.y;
        As[acq * 4 + 2][ar] = a4.z;
        As[acq * 4 + 3][ar] = a4.w;
        *reinterpret_cast<float4*>(&Bs[bkr][bnc]) =
            *reinterpret_cast<const float4*>(&B[(size_t)(k0 + bkr) * 512 + n0 + bnc]);
        __syncthreads();
        #pragma unroll
        for (int k = 0; k < 16; k++) {
            float4 a = *reinterpret_cast<const float4*>(&As[k][ty * 4]);
            float4 b = *reinterpret_cast<const float4*>(&Bs[k][tx * 4]);
            acc[0][0] += a.x * b.x; acc[0][1] += a.x * b.y; acc[0][2] += a.x * b.z; acc[0][3] += a.x * b.w;
            acc[1][0] += a.y * b.x; acc[1][1] += a.y * b.y; acc[1][2] += a.y * b.z; acc[1][3] += a.y * b.w;
            acc[2][0] += a.z * b.x; acc[2][1] += a.z * b.y; acc[2][2] += a.z * b.z; acc[2][3] += a.z * b.w;
            acc[3][0] += a.w * b.x; acc[3][1] += a.w * b.y; acc[3][2] += a.w * b.z; acc[3][3] += a.w * b.w;
        }
        __syncthreads();
    }
    #pragma unroll
    for (int i = 0; i < 4; i++) {
        int m = m0 + ty * 4 + i;
        if (m < M) {
            float4 v = make_float4(acc[i][0], acc[i][1], acc[i][2], acc[i][3]);
            *reinterpret_cast<float4*>(&Cz[(size_t)m * 512 + n0 + tx * 4]) = v;
        }
    }
}

// fold1: z<SK1 -> T1 = U@w3 chunk (U gathered inline), else T2 = w2@w1 chunk
__global__ __launch_bounds__(256) void gemm_fold1(
    const float* __restrict__ w3, const float* __restrict__ w2,
    const float* __restrict__ w1, const float* __restrict__ wn,
    const float* __restrict__ wr)
{
    int zz = blockIdx.z;
    int zk = zz & (SK1 - 1);
    if (zz < SK1)
        gemm_body_t<1, 64>(nullptr, w3, wn, wr, g_T1p + (size_t)zk * T1E, RROWS, zk * 64);
    else
        gemm_body_t<0, 64>(w2, w1, nullptr, nullptr, g_T2p + (size_t)zk * T2E, CC, zk * 64);
}

// reduce split-K partials (coalesced, vectorized)
__global__ void reduce_t() {
    int i = blockIdx.x * blockDim.x + threadIdx.x;
    const int T14 = T1E / 4;
    const int T24 = T2E / 4;
    if (i < T14) {
        const float4* a = reinterpret_cast<const float4*>(g_T1p);
        float4 v = a[i];
        #pragma unroll
        for (int s = 1; s < SK1; s++) {
            float4 w = a[s * T14 + i];
            v.x += w.x; v.y += w.y; v.z += w.z; v.w += w.w;
        }
        reinterpret_cast<float4*>(g_T1r)[i] = v;
    } else if (i < T14 + T24) {
        int j = i - T14;
        const float4* a = reinterpret_cast<const float4*>(g_T2p);
        float4 v = a[j];
        #pragma unroll
        for (int s = 1; s < SK1; s++) {
            float4 w = a[s * T24 + j];
            v.x += w.x; v.y += w.y; v.z += w.z; v.w += w.w;
        }
        reinterpret_cast<float4*>(g_T2r)[j] = v;
    }
}

// fold2: G1p[z] = T1r @ T2r chunk
__global__ __launch_bounds__(256) void gemm_fold2() {
    int zk = blockIdx.z;
    gemm_body_t<0, 64>(g_T1r, g_T2r, nullptr, nullptr,
                       g_G1p + (size_t)zk * T1E, RROWS, zk * 64);
}

// ---------------- build_bsp: separable sparse ROI fold ----------------------
__global__ __launch_bounds__(256) void build_bsp() {
    __shared__ float G[ROI][65];
    __shared__ int   ia[14], ib[14];
    __shared__ float wa[14], wb[14];
    int t  = blockIdx.y;
    int c0 = blockIdx.x * 64;
    int tid = threadIdx.x;

    if (tid < 14) {
        int y = tid;
        int cnt = 0, pA = 0, pB = 0;
        float fA = 0.f, fB = 0.f;
        #pragma unroll
        for (int pi = 0; pi < 7; pi++) {
            float yc = 3.0f / 7.0f + pi * (13.0f / 7.0f);
            float y0f = floorf(yc);
            int y0 = (int)y0f;
            float wy = yc - y0f;
            if (y == y0)     { if (cnt == 0) { pA = pi; fA = 1.f - wy; } else { pB = pi; fB = 1.f - wy; } cnt++; }
            if (y == y0 + 1) { if (cnt == 0) { pA = pi; fA = wy; }       else { pB = pi; fB = wy; }       cnt++; }
        }
        ia[y] = pA; wa[y] = fA; ib[y] = pB; wb[y] = fB;
    }
    for (int i = tid; i < ROI * 64; i += 256) {
        int p = i >> 6, cc = i & 63;
        size_t gi = (size_t)(t * ROI + p) * CC + c0 + cc;
        float g = g_G1p[gi];
        #pragma unroll
        for (int s = 1; s < SK2; s++) g += g_G1p[(size_t)s * T1E + gi];
        G[p][cc] = g;
    }
    __syncthreads();
    for (int i = tid; i < 64 * HW; i += 256) {
        int cc = i / HW, hw = i - cc * HW;
        int y = hw / WW, x = hw - y * WW;
        int   ya = ia[y], yb = ib[y];
        float fya = wa[y], fyb = wb[y];
        int   xa = ia[x], xb = ib[x];
        float fxa = wa[x], fxb = wb[x];
        float acc = fya * fxa * G[ya * 7 + xa][cc]
                  + fya * fxb * G[ya * 7 + xb][cc]
                  + fyb * fxa * G[yb * 7 + xa][cc]
                  + fyb * fxb * G[yb * 7 + xb][cc];
        g_Bsp[((size_t)t * CC + c0 + cc) * HW + hw] = acc;
    }
}

// ---------------- main pass: 1 img x 5 out per thread, high occupancy -------
// tid = h(1b) | g(3b) | l(4b): l = k lane, g = image, h = output half.
// Warp covers 2 images (same h) -> bs LDS broadcasts across halves.
__global__ __launch_bounds__(256, 5) void main_gemm(const float* __restrict__ proj) {
    __shared__ ulonglong2 bs[2][TOUT][KSTEP];     // 2 x 17.9 KB
    int n0 = blockIdx.x * NIMG;
    int sc = blockIdx.y;
    int tid = threadIdx.x;
    int l = tid & 15;
    int g = (tid >> 4) & 7;
    int h = tid >> 7;
    const ulonglong2* P  = reinterpret_cast<const ulonglong2*>(proj);
    const ulonglong2* Bv = reinterpret_cast<const ulonglong2*>(g_Bsp);
    int kbase = sc * KC4;
    int tb = h * 5;

    size_t pb = (size_t)(n0 + g) * KV4 + kbase;

    unsigned long long acc[5];
    #pragma unroll
    for (int t = 0; t < 5; t++) acc[t] = 0ull;

    auto stage_fill = [&](int s) {
        int koff = kbase + s * KSTEP;
        #pragma unroll
        for (int q = 0; q < 5; q++) {
            int i = tid + q * 256;
            if (i < TOUT * KSTEP) {
                int t = i / KSTEP, f = i - t * KSTEP;
                uint32_t dst = smem_u32(&bs[s & 1][t][f]);
                const ulonglong2* src = &Bv[(size_t)t * KV4 + koff + f];
                asm volatile("cp.async.cg.shared.global [%0], [%1], 16;"
                             :: "r"(dst), "l"(src) : "memory");
            }
        }
        asm volatile("cp.async.commit_group;" ::: "memory");
    };

    stage_fill(0);
    #pragma unroll 1
    for (int st = 0; st < NSTEP; st++) {
        if (st + 1 < NSTEP) {
            stage_fill(st + 1);
            asm volatile("cp.async.wait_group 1;" ::: "memory");
        } else {
            asm volatile("cp.async.wait_group 0;" ::: "memory");
        }
        __syncthreads();
        int koff = st * KSTEP;
        int b = st & 1;
        #pragma unroll
        for (int kk = 0; kk < 7; kk++) {
            int fo = kk * 16 + l;
            ulonglong2 p = P[pb + koff + fo];
            #pragma unroll
            for (int t = 0; t < 5; t++) {
                ulonglong2 bb = bs[b][tb + t][fo];
                acc[t] = ffma2(p.x, bb.x, acc[t]);
                acc[t] = ffma2(p.y, bb.y, acc[t]);
            }
        }
        __syncthreads();   // protect buffer b before stage st+2 overwrites it
    }

    // reduce across the 16 k-lanes of each image segment
    #pragma unroll
    for (int t = 0; t < 5; t++) {
        float v = unpack_sum(acc[t]);
        v += __shfl_down_sync(0xffffffffu, v, 8, 16);
        v += __shfl_down_sync(0xffffffffu, v, 4, 16);
        v += __shfl_down_sync(0xffffffffu, v, 2, 16);
        v += __shfl_down_sync(0xffffffffu, v, 1, 16);
        if (l == 0)
            g_part[((size_t)sc * NN + n0 + g) * TOUT + tb + t] = v;
    }
}

// ---------------- bias chain ----------------
__global__ void matvec512(const float* __restrict__ W, const float* __restrict__ v,
                          const float* __restrict__ b, float* __restrict__ out) {
    int warp = threadIdx.x >> 5, lane = threadIdx.x & 31;
    int i = blockIdx.x * 8 + warp;
    float s = 0.f;
    for (int k = lane; k < CC; k += 32) s += W[i * CC + k] * v[k];
    #pragma unroll
    for (int o = 16; o; o >>= 1) s += __shfl_down_sync(0xffffffffu, s, o);
    if (lane == 0) out[i] = s + b[i];
}

__global__ void bias_final_part(const float* __restrict__ wn, const float* __restrict__ wr) {
    int t = blockIdx.x;
    int z = blockIdx.y;
    const float* w = (t < 2) ? wn + t * (CC * ROI) : wr + (t - 2) * (CC * ROI);
    const int CHK = CC * ROI / BZ;   // 3136
    int lo = z * CHK;
    float s = 0.f;
    for (int i = lo + threadIdx.x; i < lo + CHK; i += 256) s += w[i] * g_beta3[i / ROI];
    int lane = threadIdx.x & 31, warp = threadIdx.x >> 5;
    #pragma unroll
    for (int o = 16; o; o >>= 1) s += __shfl_down_sync(0xffffffffu, s, o);
    __shared__ float red[8];
    if (lane == 0) red[warp] = s;
    __syncthreads();
    if (threadIdx.x == 0) {
        float tot = 0.f;
        #pragma unroll
        for (int w8 = 0; w8 < 8; w8++) tot += red[w8];
        g_bfp[t * BZ + z] = tot;
    }
}

// ---------------- finalize ----------------
__global__ void finalize(const float* __restrict__ bn, const float* __restrict__ br,
                         float* __restrict__ out) {
    int idx = blockIdx.x * blockDim.x + threadIdx.x;
    if (idx >= NN * TOUT) return;
    int n = idx / TOUT, t = idx % TOUT;
    float v = (t < 2) ? bn[t] : br[t - 2];
    #pragma unroll
    for (int z = 0; z < BZ; z++) v += g_bfp[t * BZ + z];
    #pragma unroll
    for (int sc = 0; sc < MSPLIT; sc++)
        v += g_part[((size_t)sc * NN + n) * TOUT + t];
    if (t < 2) out[n * 2 + t] = v;
    else       out[NN * 2 + n * 8 + (t - 2)] = v;
}

// ---------------- launch ----------------
extern "C" void kernel_launch(void* const* d_in, const int* in_sizes, int n_in,
                              void* d_out, int out_size) {
    const float* project = (const float*)d_in[0];
    const float* w1      = (const float*)d_in[1];
    const float* b1      = (const float*)d_in[2];
    const float* w2      = (const float*)d_in[3];
    const float* b2      = (const float*)d_in[4];
    const float* w3      = (const float*)d_in[5];
    const float* b3      = (const float*)d_in[6];
    const float* w_note  = (const float*)d_in[7];
    const float* b_note  = (const float*)d_in[8];
    const float* w_reg   = (const float*)d_in[9];
    const float* b_reg   = (const float*)d_in[10];
    float* out = (float*)d_out;

    float *pb2, *pb3;
    cudaGetSymbolAddress((void**)&pb2, g_beta2);
    cudaGetSymbolAddress((void**)&pb3, g_beta3);

    // fold chain, then main pass in the profiled slot
    gemm_fold1<<<dim3(8, 8, 2 * SK1), 256>>>(w3, w2, w1, w_note, w_reg);
    reduce_t<<<(T1E / 4 + T2E / 4 + 255) / 256, 256>>>();
    gemm_fold2<<<dim3(8, 8, SK2), 256>>>();
    build_bsp<<<dim3(8, TOUT), 256>>>();
    main_gemm<<<dim3(NN / NIMG, MSPLIT), 256>>>(project);

    // bias chain + finalize
    matvec512<<<64, 256>>>(w2, b1, b2, pb2);
    matvec512<<<64, 256>>>(w3, pb2, b3, pb3);
    bias_final_part<<<dim3(TOUT, BZ), 256>>>(w_note, w_reg);
    finalize<<<(NN * TOUT + 255) / 256, 256>>>(b_note, b_reg, out);
}

// round 15
// speedup vs baseline: 1.4249x; 1.4249x over previous
#include <cuda_runtime.h>
#include <cuda_bf16.h>
#include <cstdint>

// Problem constants
#define NN 512
#define CC 512
#define HH 14
#define WW 14
#define HW 196
#define ROI 49
#define RROWS 490            // 10*49
#define TOUT 10
#define CHW 100352           // 512*196
#define KV4 25088            // CHW in 16B units
#define SK1 4                // split-K for fold1 (K-chunk 128)
#define SK2 8                // split-K for fold2 (K-chunk 64)
#define MSPLIT 16            // K splits for main pass
#define KC4 1568             // KV4/MSPLIT (16B units)
#define KSTEP 112            // 16B units per stage step
#define NSTEP 14             // KC4/KSTEP
#define NIMG 16              // images per block in main pass
#define BZ 8                 // bias_final chunks

#define T1E (RROWS * CC)     // 250880
#define T2E (CC * CC)        // 262144

// ---------------- device scratch ----------------
__device__ __align__(16) float g_T1p[SK1 * T1E];
__device__ __align__(16) float g_T2p[SK1 * T2E];
__device__ __align__(16) float g_G1p[SK2 * T1E];
__device__ __align__(16) float g_G1r[T1E];
__device__ __align__(16) float g_Bsp[TOUT * CHW];
__device__ float g_beta2[CC];
__device__ float g_beta3[CC];
__device__ float g_bfp[TOUT * BZ];
__device__ float g_part[MSPLIT * NN * TOUT];

// packed fp32x2 FMA (Blackwell)
__device__ __forceinline__ unsigned long long ffma2(
    unsigned long long a, unsigned long long b, unsigned long long c)
{
    unsigned long long d;
    asm("fma.rn.f32x2 %0, %1, %2, %3;" : "=l"(d) : "l"(a), "l"(b), "l"(c));
    return d;
}

__device__ __forceinline__ float unpack_sum(unsigned long long v) {
    float lo, hi;
    asm("mov.b64 {%0, %1}, %2;" : "=f"(lo), "=f"(hi) : "l"(v));
    return lo + hi;
}

// ---------------- GEMM body (templated A/B sourcing) ------------------------
// MODE 0: plain A,B. MODE 1: A gathered from heads. MODE 2: A,B = SK1-summed partials.
template<int MODE, int KCH>
__device__ __forceinline__ void gemm_body_t(
    const float* __restrict__ A, const float* __restrict__ B,
    const float* __restrict__ wn, const float* __restrict__ wr,
    float* __restrict__ Cz, int M, int kbase)
{
    __shared__ float As[16][64];
    __shared__ float Bs[16][64];
    int tid = threadIdx.x;
    int m0 = blockIdx.y * 64;
    int n0 = blockIdx.x * 64;

    int ar  = tid >> 2;
    int acq = tid & 3;
    int bkr = tid >> 4;
    int bnc = (tid & 15) * 4;
    int ty  = tid >> 4;
    int tx  = tid & 15;

    float acc[4][4] = {};
    #pragma unroll 1
    for (int kk = 0; kk < KCH; kk += 16) {
        int k0 = kbase + kk;
        float4 a4 = make_float4(0.f, 0.f, 0.f, 0.f);
        int m = m0 + ar;
        if (m < M) {
            if (MODE == 1) {
                int t = m / ROI, p = m % ROI;
                const float* wsrc = (t < 2) ? wn + t * (CC * ROI) + p
                                            : wr + (t - 2) * (CC * ROI) + p;
                int o = k0 + acq * 4;
                a4.x = wsrc[(o + 0) * ROI];
                a4.y = wsrc[(o + 1) * ROI];
                a4.z = wsrc[(o + 2) * ROI];
                a4.w = wsrc[(o + 3) * ROI];
            } else if (MODE == 2) {
                size_t ai = (size_t)m * 512 + k0 + acq * 4;
                a4 = *reinterpret_cast<const float4*>(&A[ai]);
                #pragma unroll
                for (int s = 1; s < SK1; s++) {
                    float4 w4 = *reinterpret_cast<const float4*>(&A[(size_t)s * T1E + ai]);
                    a4.x += w4.x; a4.y += w4.y; a4.z += w4.z; a4.w += w4.w;
                }
            } else {
                a4 = *reinterpret_cast<const float4*>(&A[(size_t)m * 512 + k0 + acq * 4]);
            }
        }
        As[acq * 4 + 0][ar] = a4.x;
        As[acq * 4 + 1][ar] = a4.y;
        As[acq * 4 + 2][ar] = a4.z;
        As[acq * 4 + 3][ar] = a4.w;

        float4 b4;
        {
            size_t bi = (size_t)(k0 + bkr) * 512 + n0 + bnc;
            b4 = *reinterpret_cast<const float4*>(&B[bi]);
            if (MODE == 2) {
                #pragma unroll
                for (int s = 1; s < SK1; s++) {
                    float4 w4 = *reinterpret_cast<const float4*>(&B[(size_t)s * T2E + bi]);
                    b4.x += w4.x; b4.y += w4.y; b4.z += w4.z; b4.w += w4.w;
                }
            }
        }
        *reinterpret_cast<float4*>(&Bs[bkr][bnc]) = b4;
        __syncthreads();
        #pragma unroll
        for (int k = 0; k < 16; k++) {
            float4 a = *reinterpret_cast<const float4*>(&As[k][ty * 4]);
            float4 b = *reinterpret_cast<const float4*>(&Bs[k][tx * 4]);
            acc[0][0] += a.x * b.x; acc[0][1] += a.x * b.y; acc[0][2] += a.x * b.z; acc[0][3] += a.x * b.w;
            acc[1][0] += a.y * b.x; acc[1][1] += a.y * b.y; acc[1][2] += a.y * b.z; acc[1][3] += a.y * b.w;
            acc[2][0] += a.z * b.x; acc[2][1] += a.z * b.y; acc[2][2] += a.z * b.z; acc[2][3] += a.z * b.w;
            acc[3][0] += a.w * b.x; acc[3][1] += a.w * b.y; acc[3][2] += a.w * b.z; acc[3][3] += a.w * b.w;
        }
        __syncthreads();
    }
    #pragma unroll
    for (int i = 0; i < 4; i++) {
        int m = m0 + ty * 4 + i;
        if (m < M) {
            float4 v = make_float4(acc[i][0], acc[i][1], acc[i][2], acc[i][3]);
            *reinterpret_cast<float4*>(&Cz[(size_t)m * 512 + n0 + tx * 4]) = v;
        }
    }
}

// fold1: z<SK1 -> T1 = U@w3 chunk (U gathered inline), else T2 = w2@w1 chunk
__global__ __launch_bounds__(256) void gemm_fold1(
    const float* __restrict__ w3, const float* __restrict__ w2,
    const float* __restrict__ w1, const float* __restrict__ wn,
    const float* __restrict__ wr)
{
    int zz = blockIdx.z;
    int zk = zz & (SK1 - 1);
    if (zz < SK1)
        gemm_body_t<1, 128>(nullptr, w3, wn, wr, g_T1p + (size_t)zk * T1E, RROWS, zk * 128);
    else
        gemm_body_t<0, 128>(w2, w1, nullptr, nullptr, g_T2p + (size_t)zk * T2E, CC, zk * 128);
}

// fold2: G1p[z] = (sum T1p) @ (sum T2p) chunk, partial sums fused into loads
__global__ __launch_bounds__(256) void gemm_fold2() {
    int zk = blockIdx.z;   // 0..SK2-1
    gemm_body_t<2, 64>(g_T1p, g_T2p, nullptr, nullptr,
                       g_G1p + (size_t)zk * T1E, RROWS, zk * 64);
}

// ---------------- reduce_g1: sum SK2 partials of G1 (coalesced) -------------
__global__ void reduce_g1() {
    int i = blockIdx.x * blockDim.x + threadIdx.x;
    const int T14 = T1E / 4;     // 62720
    if (i >= T14) return;
    const float4* a = reinterpret_cast<const float4*>(g_G1p);
    float4 v = a[i];
    #pragma unroll
    for (int s = 1; s < SK2; s++) {
        float4 w = a[s * T14 + i];
        v.x += w.x; v.y += w.y; v.z += w.z; v.w += w.w;
    }
    reinterpret_cast<float4*>(g_G1r)[i] = v;
}

// ---------------- build_bsp: separable sparse ROI fold ----------------------
// grid (16, 10, 2): 32-channel tile x head x hw-half -> 320 blocks.
__global__ __launch_bounds__(256) void build_bsp() {
    __shared__ float G[ROI][33];
    __shared__ int   ia[14], ib[14];
    __shared__ float wa[14], wb[14];
    int t  = blockIdx.y;
    int c0 = blockIdx.x * 32;
    int hw0 = blockIdx.z * 98;
    int tid = threadIdx.x;

    if (tid < 14) {
        int y = tid;
        int cnt = 0, pA = 0, pB = 0;
        float fA = 0.f, fB = 0.f;
        #pragma unroll
        for (int pi = 0; pi < 7; pi++) {
            float yc = 3.0f / 7.0f + pi * (13.0f / 7.0f);
            float y0f = floorf(yc);
            int y0 = (int)y0f;
            float wy = yc - y0f;
            if (y == y0)     { if (cnt == 0) { pA = pi; fA = 1.f - wy; } else { pB = pi; fB = 1.f - wy; } cnt++; }
            if (y == y0 + 1) { if (cnt == 0) { pA = pi; fA = wy; }       else { pB = pi; fB = wy; }       cnt++; }
        }
        ia[y] = pA; wa[y] = fA; ib[y] = pB; wb[y] = fB;
    }
    for (int i = tid; i < ROI * 32; i += 256) {
        int p = i >> 5, cc = i & 31;
        G[p][cc] = g_G1r[(size_t)(t * ROI + p) * CC + c0 + cc];
    }
    __syncthreads();
    for (int i = tid; i < 32 * 98; i += 256) {
        int cc = i / 98, hw = hw0 + (i - cc * 98);
        int y = hw / WW, x = hw - y * WW;
        int   ya = ia[y], yb = ib[y];
        float fya = wa[y], fyb = wb[y];
        int   xa = ia[x], xb = ib[x];
        float fxa = wa[x], fxb = wb[x];
        float acc = fya * fxa * G[ya * 7 + xa][cc]
                  + fya * fxb * G[ya * 7 + xb][cc]
                  + fyb * fxa * G[yb * 7 + xa][cc]
                  + fyb * fxb * G[yb * 7 + xb][cc];
        g_Bsp[((size_t)t * CC + c0 + cc) * HW + hw] = acc;
    }
}

// ---------------- main pass: R11 version (82.5us measured) ------------------
// 256 threads = 8 image-groups(g) x 2 output-halves(h) x 16 k-lanes(l),
// h at bit 4 so each image is read by exactly 16 lanes per half-pair warp.
__global__ __launch_bounds__(256, 4) void main_gemm(const float* __restrict__ proj) {
    __shared__ ulonglong2 bs[TOUT][KSTEP];      // 17.9 KB
    int n0 = blockIdx.x * NIMG;
    int sc = blockIdx.y;
    int tid = threadIdx.x;
    int l = tid & 15;
    int h = (tid >> 4) & 1;
    int g = tid >> 5;
    const ulonglong2* P  = reinterpret_cast<const ulonglong2*>(proj);
    const ulonglong2* Bv = reinterpret_cast<const ulonglong2*>(g_Bsp);
    int kbase = sc * KC4;
    int tb = h * 5;

    size_t pb0 = (size_t)(n0 + g * 2 + 0) * KV4 + kbase;
    size_t pb1 = (size_t)(n0 + g * 2 + 1) * KV4 + kbase;

    unsigned long long acc[2][5];
    #pragma unroll
    for (int i = 0; i < 2; i++)
        #pragma unroll
        for (int t = 0; t < 5; t++) acc[i][t] = 0ull;

    for (int st = 0; st < NSTEP; st++) {
        int koff = st * KSTEP;
        if (st) __syncthreads();
        for (int i = tid; i < TOUT * KSTEP; i += 256) {
            int t = i / KSTEP, f = i - t * KSTEP;
            bs[t][f] = Bv[(size_t)t * KV4 + kbase + koff + f];
        }
        __syncthreads();
        #pragma unroll
        for (int kk = 0; kk < 7; kk++) {
            int fo = kk * 16 + l;
            ulonglong2 p0 = P[pb0 + koff + fo];
            ulonglong2 p1 = P[pb1 + koff + fo];
            #pragma unroll
            for (int t = 0; t < 5; t++) {
                ulonglong2 b = bs[tb + t][fo];
                acc[0][t] = ffma2(p0.x, b.x, acc[0][t]);
                acc[0][t] = ffma2(p0.y, b.y, acc[0][t]);
                acc[1][t] = ffma2(p1.x, b.x, acc[1][t]);
                acc[1][t] = ffma2(p1.y, b.y, acc[1][t]);
            }
        }
    }

    // reduce across the 16 k-lanes of each (g,h) segment
    #pragma unroll
    for (int i = 0; i < 2; i++) {
        #pragma unroll
        for (int t = 0; t < 5; t++) {
            float v = unpack_sum(acc[i][t]);
            v += __shfl_down_sync(0xffffffffu, v, 8, 16);
            v += __shfl_down_sync(0xffffffffu, v, 4, 16);
            v += __shfl_down_sync(0xffffffffu, v, 2, 16);
            v += __shfl_down_sync(0xffffffffu, v, 1, 16);
            if (l == 0)
                g_part[((size_t)sc * NN + n0 + g * 2 + i) * TOUT + tb + t] = v;
        }
    }
}

// ---------------- bias chain ----------------
__global__ void matvec512(const float* __restrict__ W, const float* __restrict__ v,
                          const float* __restrict__ b, float* __restrict__ out) {
    int warp = threadIdx.x >> 5, lane = threadIdx.x & 31;
    int i = blockIdx.x * 8 + warp;
    float s = 0.f;
    for (int k = lane; k < CC; k += 32) s += W[i * CC + k] * v[k];
    #pragma unroll
    for (int o = 16; o; o >>= 1) s += __shfl_down_sync(0xffffffffu, s, o);
    if (lane == 0) out[i] = s + b[i];
}

__global__ void bias_final_part(const float* __restrict__ wn, const float* __restrict__ wr) {
    int t = blockIdx.x;
    int z = blockIdx.y;
    const float* w = (t < 2) ? wn + t * (CC * ROI) : wr + (t - 2) * (CC * ROI);
    const int CHK = CC * ROI / BZ;   // 3136
    int lo = z * CHK;
    float s = 0.f;
    for (int i = lo + threadIdx.x; i < lo + CHK; i += 256) s += w[i] * g_beta3[i / ROI];
    int lane = threadIdx.x & 31, warp = threadIdx.x >> 5;
    #pragma unroll
    for (int o = 16; o; o >>= 1) s += __shfl_down_sync(0xffffffffu, s, o);
    __shared__ float red[8];
    if (lane == 0) red[warp] = s;
    __syncthreads();
    if (threadIdx.x == 0) {
        float tot = 0.f;
        #pragma unroll
        for (int w8 = 0; w8 < 8; w8++) tot += red[w8];
        g_bfp[t * BZ + z] = tot;
    }
}

// ---------------- finalize ----------------
__global__ void finalize(const float* __restrict__ bn, const float* __restrict__ br,
                         float* __restrict__ out) {
    int idx = blockIdx.x * blockDim.x + threadIdx.x;
    if (idx >= NN * TOUT) return;
    int n = idx / TOUT, t = idx % TOUT;
    float v = (t < 2) ? bn[t] : br[t - 2];
    #pragma unroll
    for (int z = 0; z < BZ; z++) v += g_bfp[t * BZ + z];
    #pragma unroll
    for (int sc = 0; sc < MSPLIT; sc++)
        v += g_part[((size_t)sc * NN + n) * TOUT + t];
    if (t < 2) out[n * 2 + t] = v;
    else       out[NN * 2 + n * 8 + (t - 2)] = v;
}

// ---------------- launch ----------------
extern "C" void kernel_launch(void* const* d_in, const int* in_sizes, int n_in,
                              void* d_out, int out_size) {
    const float* project = (const float*)d_in[0];
    const float* w1      = (const float*)d_in[1];
    const float* b1      = (const float*)d_in[2];
    const float* w2      = (const float*)d_in[3];
    const float* b2      = (const float*)d_in[4];
    const float* w3      = (const float*)d_in[5];
    const float* b3      = (const float*)d_in[6];
    const float* w_note  = (const float*)d_in[7];
    const float* b_note  = (const float*)d_in[8];
    const float* w_reg   = (const float*)d_in[9];
    const float* b_reg   = (const float*)d_in[10];
    float* out = (float*)d_out;

    float *pb2, *pb3;
    cudaGetSymbolAddress((void**)&pb2, g_beta2);
    cudaGetSymbolAddress((void**)&pb3, g_beta3);

    // fold chain
    gemm_fold1<<<dim3(8, 8, 2 * SK1), 256>>>(w3, w2, w1, w_note, w_reg);
    gemm_fold2<<<dim3(8, 8, SK2), 256>>>();
    reduce_g1<<<(T1E / 4 + 255) / 256, 256>>>();
    build_bsp<<<dim3(16, TOUT, 2), 256>>>();
    main_gemm<<<dim3(NN / NIMG, MSPLIT), 256>>>(project);

    // bias chain + finalize
    matvec512<<<64, 256>>>(w2, b1, b2, pb2);
    matvec512<<<64, 256>>>(w3, pb2, b3, pb3);
    bias_final_part<<<dim3(TOUT, BZ), 256>>>(w_note, w_reg);
    finalize<<<(NN * TOUT + 255) / 256, 256>>>(b_note, b_reg, out);
}